// round 16
// baseline (speedup 1.0000x reference)
#include <cuda_runtime.h>
#include <cuda_bf16.h>
#include <math.h>
#include <stdint.h>

#define B_  32
#define S_  512
#define E_  256
#define H_  8
#define DH_ 32
#define L_  4
#define FF_ 1024
#define BS_ (B_ * S_)          // 16384 rows
#define EPS_ 1e-5f

// ---------------- scratch (allocation-free: __device__ globals) ----------------
__device__ float g_h  [BS_ * E_];
__device__ float g_xn [BS_ * E_];
__device__ float g_att[BS_ * E_];
__device__ float g_res[BS_ * E_];
// attention buffers: plain bf16 (error analysis: contributes ~1e-5 to residual)
__device__ __align__(256) __nv_bfloat16 g_qb [BS_ * E_];   // [bh][s][32], pre-scaled
__device__ __align__(256) __nv_bfloat16 g_kb [BS_ * E_];   // [bh][s][32]
__device__ __align__(256) __nv_bfloat16 g_vtb[BS_ * E_];   // [bh][d][s]  (transposed)
// FFN buffers: bf16 hi/lo 3-term split (feeds output at magnitude ~1)
__device__ __align__(256) __nv_bfloat16 g_rnh[BS_ * E_];
__device__ __align__(256) __nv_bfloat16 g_rnl[BS_ * E_];
__device__ __align__(256) __nv_bfloat16 g_ffh[BS_ * FF_];
__device__ __align__(256) __nv_bfloat16 g_ffl[BS_ * FF_];
__device__ __align__(256) __nv_bfloat16 g_w1h[L_ * FF_ * E_];   // [l][n=FF][k=E]
__device__ __align__(256) __nv_bfloat16 g_w1l[L_ * FF_ * E_];
__device__ __align__(256) __nv_bfloat16 g_w2h[L_ * E_ * FF_];   // [l][n=E][k=FF]
__device__ __align__(256) __nv_bfloat16 g_w2l[L_ * E_ * FF_];

// ---------------- mma.sync / cp.async helpers ----------------
__device__ __forceinline__ uint32_t s2u(const void* p) {
    uint32_t a;
    asm("{ .reg .u64 t; cvta.to.shared.u64 t, %1; cvt.u32.u64 %0, t; }" : "=r"(a) : "l"(p));
    return a;
}
__device__ __forceinline__ void ldsm4(uint32_t* r, uint32_t a) {
    asm volatile("ldmatrix.sync.aligned.m8n8.x4.shared.b16 {%0,%1,%2,%3}, [%4];"
                 : "=r"(r[0]), "=r"(r[1]), "=r"(r[2]), "=r"(r[3]) : "r"(a));
}
__device__ __forceinline__ void mma16816(float* c, const uint32_t* a, const uint32_t* b) {
    asm volatile("mma.sync.aligned.m16n8k16.row.col.f32.bf16.bf16.f32 "
                 "{%0,%1,%2,%3}, {%4,%5,%6,%7}, {%8,%9}, {%0,%1,%2,%3};"
                 : "+f"(c[0]), "+f"(c[1]), "+f"(c[2]), "+f"(c[3])
                 : "r"(a[0]), "r"(a[1]), "r"(a[2]), "r"(a[3]), "r"(b[0]), "r"(b[1]));
}
__device__ __forceinline__ void cp16(uint32_t d, const void* s) {
    asm volatile("cp.async.ca.shared.global [%0], [%1], 16;" :: "r"(d), "l"(s));
}
#define CP_COMMIT() asm volatile("cp.async.commit_group;" ::: "memory")
#define CP_WAIT(n)  asm volatile("cp.async.wait_group %0;" :: "n"(n) : "memory")

__device__ __forceinline__ void hilo2(float x, float y, uint32_t& hi, uint32_t& lo) {
    __nv_bfloat16 hx = __float2bfloat16(x), hy = __float2bfloat16(y);
    __nv_bfloat162 h2, l2;
    h2.x = hx; h2.y = hy;
    l2.x = __float2bfloat16(x - __bfloat162float(hx));
    l2.y = __float2bfloat16(y - __bfloat162float(hy));
    hi = *(uint32_t*)&h2; lo = *(uint32_t*)&l2;
}
__device__ __forceinline__ uint32_t pack2bf(float x, float y) {
    __nv_bfloat162 h2;
    h2.x = __float2bfloat16(x); h2.y = __float2bfloat16(y);
    return *(uint32_t*)&h2;
}
__device__ __forceinline__ float warp_sum(float v) {
    #pragma unroll
    for (int o = 16; o; o >>= 1) v += __shfl_xor_sync(0xffffffffu, v, o);
    return v;
}

// smem tile pitches (bf16 elems)
#define TP_  72    // 64 k-elems + 8  (V tiles in attention)
#define QP_  40    // 32 k-elems + 8  (Q/K tiles + gemm K-chunk-32 tiles)
#define GTSZ_ (128 * QP_)                      // one gemm tile: 5120 elems
#define GSTG_ (4 * GTSZ_)                      // gemm stage (Ah,Al,Bh,Bl): 20480
#define SMEM_DYN (2 * GSTG_ * 2)               // 2 stages = 81920 B -> 2 CTA/SM

// attention dynamic smem layout (elem offsets) -- plain bf16, 2-stage K/V
#define AQ_  0
#define AK_(s) (128 * QP_ + (s) * 64 * QP_)
#define AV_(s) (128 * QP_ + 2 * 64 * QP_ + (s) * 32 * TP_)
#define ATT_SMEM ((128 * QP_ + 2 * 64 * QP_ + 2 * 32 * TP_) * 2)   // 29696 B

// ---------------- elementwise / norm kernels ----------------
__global__ void k_addpos(const float* __restrict__ x, const float* __restrict__ pos) {
    int i = blockIdx.x * blockDim.x + threadIdx.x;
    g_h[i] = x[i] + pos[i & (E_ - 1)];
}

// warp-per-row LayerNorm: 8 rows/block, shfl-only reductions
__global__ __launch_bounds__(256) void k_ln(const float* __restrict__ src,
                                            float* __restrict__ dst) {
    int w = threadIdx.x >> 5, lane = threadIdx.x & 31;
    int row = blockIdx.x * 8 + w;
    const float* p = src + (size_t)row * E_ + lane * 8;
    float4 a = *(const float4*)p;
    float4 b = *(const float4*)(p + 4);
    float s = (a.x + a.y) + (a.z + a.w) + (b.x + b.y) + (b.z + b.w);
    float m = warp_sum(s) * (1.0f / E_);
    a.x -= m; a.y -= m; a.z -= m; a.w -= m;
    b.x -= m; b.y -= m; b.z -= m; b.w -= m;
    float q = a.x * a.x + a.y * a.y + a.z * a.z + a.w * a.w
            + b.x * b.x + b.y * b.y + b.z * b.z + b.w * b.w;
    float r = rsqrtf(warp_sum(q) * (1.0f / E_) + EPS_);
    a.x *= r; a.y *= r; a.z *= r; a.w *= r;
    b.x *= r; b.y *= r; b.z *= r; b.w *= r;
    float* q_ = dst + (size_t)row * E_ + lane * 8;
    *(float4*)q_ = a;
    *(float4*)(q_ + 4) = b;
}

// res = a + b ; rn = LayerNorm(res) -> bf16 hi/lo. warp-per-row.
__global__ __launch_bounds__(256) void k_add_ln(const float* __restrict__ A,
                                                const float* __restrict__ Bp,
                                                float* __restrict__ res,
                                                __nv_bfloat16* __restrict__ rnh,
                                                __nv_bfloat16* __restrict__ rnl) {
    int w = threadIdx.x >> 5, lane = threadIdx.x & 31;
    int row = blockIdx.x * 8 + w;
    size_t off = (size_t)row * E_ + lane * 8;
    float4 a0 = *(const float4*)(A + off);
    float4 a1 = *(const float4*)(A + off + 4);
    float4 b0 = *(const float4*)(Bp + off);
    float4 b1 = *(const float4*)(Bp + off + 4);
    a0.x += b0.x; a0.y += b0.y; a0.z += b0.z; a0.w += b0.w;
    a1.x += b1.x; a1.y += b1.y; a1.z += b1.z; a1.w += b1.w;
    *(float4*)(res + off) = a0;
    *(float4*)(res + off + 4) = a1;
    float s = (a0.x + a0.y) + (a0.z + a0.w) + (a1.x + a1.y) + (a1.z + a1.w);
    float m = warp_sum(s) * (1.0f / E_);
    float y[8] = { a0.x - m, a0.y - m, a0.z - m, a0.w - m,
                   a1.x - m, a1.y - m, a1.z - m, a1.w - m };
    float q = 0.f;
    #pragma unroll
    for (int j = 0; j < 8; j++) q += y[j] * y[j];
    float r = rsqrtf(warp_sum(q) * (1.0f / E_) + EPS_);
    __align__(16) __nv_bfloat16 hv[8], lv[8];
    #pragma unroll
    for (int j = 0; j < 8; j++) {
        float v = y[j] * r;
        hv[j] = __float2bfloat16(v);
        lv[j] = __float2bfloat16(v - __bfloat162float(hv[j]));
    }
    *(uint4*)(rnh + off) = *(uint4*)hv;
    *(uint4*)(rnl + off) = *(uint4*)lv;
}

// weight transpose + hi/lo bf16 split: W[l][K][N] fp32 -> T{hi,lo}[l][N][K]
__global__ __launch_bounds__(256) void k_wconv(const float* __restrict__ W,
                                               __nv_bfloat16* __restrict__ Thi,
                                               __nv_bfloat16* __restrict__ Tlo,
                                               int K, int N) {
    __shared__ float t[32][33];
    int l = blockIdx.z;
    const float* Wl = W + (size_t)l * K * N;
    __nv_bfloat16* Hl = Thi + (size_t)l * K * N;
    __nv_bfloat16* Ll = Tlo + (size_t)l * K * N;
    int tx = threadIdx.x & 31, ty = threadIdx.x >> 5;
    int k0 = blockIdx.y * 32, n0 = blockIdx.x * 32;
    #pragma unroll
    for (int i = 0; i < 4; i++)
        t[ty + i * 8][tx] = Wl[(size_t)(k0 + ty + i * 8) * N + n0 + tx];
    __syncthreads();
    #pragma unroll
    for (int i = 0; i < 4; i++) {
        int n = n0 + ty + i * 8;
        float v = t[tx][ty + i * 8];
        __nv_bfloat16 hi = __float2bfloat16(v);
        Hl[(size_t)n * K + k0 + tx] = hi;
        Ll[(size_t)n * K + k0 + tx] = __float2bfloat16(v - __bfloat162float(hi));
    }
}

// ---------------- QKV projection: fp32 SIMT compute, plain bf16 outputs -------
__global__ __launch_bounds__(256) void k_qkv(const float* __restrict__ xn,
                                             const float* __restrict__ Wq,
                                             const float* __restrict__ Wk,
                                             const float* __restrict__ Wv) {
    __shared__ __align__(16) float Xs[64 * 32];
    __shared__ __align__(16) float WsQ[32 * 32];
    __shared__ __align__(16) float WsK[32 * 32];
    __shared__ __align__(16) float WsV[32 * 32];
    __shared__ float vbuf[32][65];
    int tid = threadIdx.x;
    int bh = blockIdx.y;
    int b = bh >> 3, h = bh & 7;
    int s0 = blockIdx.x * 64;

    ((float4*)WsQ)[tid] = ((const float4*)(Wq + h * 1024))[tid];
    ((float4*)WsK)[tid] = ((const float4*)(Wk + h * 1024))[tid];
    ((float4*)WsV)[tid] = ((const float4*)(Wv + h * 1024))[tid];
    #pragma unroll
    for (int it = 0; it < 2; it++) {
        int fi = it * 256 + tid;
        int r = fi >> 3, d4 = fi & 7;
        float4 t = *(const float4*)(xn + (b * S_ + s0 + r) * E_ + h * 32 + d4 * 4);
        *(float4*)(Xs + r * 32 + d4 * 4) = t;
    }
    __syncthreads();

    int w = tid >> 5, lane = tid & 31;
    int r0 = w * 8;
    float aq[8] = {0}, ak[8] = {0}, av[8] = {0};
    #pragma unroll
    for (int d = 0; d < 32; d++) {
        float wq = WsQ[d * 32 + lane];
        float wk = WsK[d * 32 + lane];
        float wv = WsV[d * 32 + lane];
        #pragma unroll
        for (int r = 0; r < 8; r++) {
            float xv = Xs[(r0 + r) * 32 + d];
            aq[r] = fmaf(xv, wq, aq[r]);
            ak[r] = fmaf(xv, wk, ak[r]);
            av[r] = fmaf(xv, wv, av[r]);
        }
    }
    const float qs = 0.17677669529663687f;  // 1/sqrt(32)
    #pragma unroll
    for (int r = 0; r < 8; r++) {
        int idx = (bh * S_ + s0 + r0 + r) * DH_ + lane;
        g_qb[idx] = __float2bfloat16(aq[r] * qs);
        g_kb[idx] = __float2bfloat16(ak[r]);
        vbuf[lane][r0 + r] = av[r];
    }
    __syncthreads();
    {
        int d = tid >> 3, seg = tid & 7;
        __align__(16) __nv_bfloat16 hv[8];
        #pragma unroll
        for (int j = 0; j < 8; j++)
            hv[j] = __float2bfloat16(vbuf[d][seg * 8 + j]);
        size_t o = (size_t)(bh * DH_ + d) * S_ + s0 + seg * 8;
        *(uint4*)(g_vtb + o) = *(uint4*)hv;
    }
}

// ---------------- Flash attention, plain bf16, no-max softmax, 1 sync/iter ----
// grid (S/128, B*H), 128 threads (4 warps x 32 q-rows). Key block = 64, 2-stage.
__global__ __launch_bounds__(128) void k_attn2() {
    extern __shared__ __align__(16) __nv_bfloat16 asm_[];
    const int tid = threadIdx.x;
    const int wid = tid >> 5, lane = tid & 31;
    const int bh = blockIdx.y;
    const int q0 = blockIdx.x * 128;
    const uint32_t uS = s2u(asm_);

    // ---- stage Q via cp.async (512 x16B) ----
    #pragma unroll
    for (int it = 0; it < 4; it++) {
        int e = it * 128 + tid;
        int r = e >> 2, c = e & 3;
        cp16(uS + (AQ_ + r * QP_ + c * 8) * 2,
             g_qb + (size_t)(bh * S_ + q0 + r) * DH_ + c * 8);
    }
    CP_COMMIT();

    auto loadKV = [&](int kb, int s) {
        #pragma unroll
        for (int it = 0; it < 2; it++) {
            int e = it * 128 + tid;
            int r = e >> 2, c = e & 3;
            cp16(uS + (AK_(s) + r * QP_ + c * 8) * 2,
                 g_kb + (size_t)(bh * S_ + kb * 64 + r) * DH_ + c * 8);
            int rv = e >> 3, cv = e & 7;
            cp16(uS + (AV_(s) + rv * TP_ + cv * 8) * 2,
                 g_vtb + (size_t)(bh * DH_ + rv) * S_ + kb * 64 + cv * 8);
        }
        CP_COMMIT();
    };
    loadKV(0, 0);
    CP_WAIT(0);
    __syncthreads();

    // ---- Q fragments (registers, held across key loop) ----
    const int aRow = lane & 15, aK = (lane >> 4) << 3;
    uint32_t qf[2][2][4];
    #pragma unroll
    for (int ma = 0; ma < 2; ma++)
        #pragma unroll
        for (int kt = 0; kt < 2; kt++)
            ldsm4(qf[ma][kt],
                  uS + (uint32_t)((AQ_ + (wid * 32 + ma * 16 + aRow) * QP_ + kt * 16 + aK) * 2));

    float l[2][2], o[2][4][4];
    #pragma unroll
    for (int ma = 0; ma < 2; ma++)
        #pragma unroll
        for (int hf = 0; hf < 2; hf++) l[ma][hf] = 0.f;
    #pragma unroll
    for (int ma = 0; ma < 2; ma++)
        #pragma unroll
        for (int nd = 0; nd < 4; nd++)
            #pragma unroll
            for (int r = 0; r < 4; r++) o[ma][nd][r] = 0.f;

    for (int kb = 0; kb < S_ / 64; kb++) {
        const int st = kb & 1;
        // prefetch next block into the other stage (readers of it were fenced
        // by the previous bottom barrier)
        if (kb + 1 < S_ / 64) loadKV(kb + 1, st ^ 1);

        const uint32_t uK = uS + AK_(st) * 2;
        const uint32_t uV = uS + AV_(st) * 2;

        // ---- S = Q K^T ----
        float sc[2][8][4];
        #pragma unroll
        for (int ma = 0; ma < 2; ma++)
            #pragma unroll
            for (int na = 0; na < 8; na++)
                #pragma unroll
                for (int r = 0; r < 4; r++) sc[ma][na][r] = 0.f;

        #pragma unroll
        for (int ks = 0; ks < 2; ks++) {
            uint32_t kf[8][2];
            #pragma unroll
            for (int rg = 0; rg < 2; rg++) {
                uint32_t off0 = (uint32_t)(((rg * 32 + lane) * QP_ + ks * 16) * 2);
                uint32_t t0[4], t1[4];
                ldsm4(t0, uK + off0);
                ldsm4(t1, uK + off0 + 16);
                #pragma unroll
                for (int j = 0; j < 4; j++) {
                    kf[rg * 4 + j][0] = t0[j]; kf[rg * 4 + j][1] = t1[j];
                }
            }
            #pragma unroll
            for (int ma = 0; ma < 2; ma++)
                #pragma unroll
                for (int na = 0; na < 8; na++)
                    mma16816(sc[ma][na], qf[ma][ks], kf[na]);
        }

        // ---- p = exp(min(s,30)); accumulate per-thread partial denominator ----
        #pragma unroll
        for (int ma = 0; ma < 2; ma++) {
            float t0 = 0.f, t1 = 0.f;
            #pragma unroll
            for (int na = 0; na < 8; na++) {
                float p0 = __expf(fminf(sc[ma][na][0], 30.f));
                float p1 = __expf(fminf(sc[ma][na][1], 30.f));
                float p2 = __expf(fminf(sc[ma][na][2], 30.f));
                float p3 = __expf(fminf(sc[ma][na][3], 30.f));
                sc[ma][na][0] = p0; sc[ma][na][1] = p1;
                sc[ma][na][2] = p2; sc[ma][na][3] = p3;
                t0 += p0 + p1;
                t1 += p2 + p3;
            }
            l[ma][0] += t0;
            l[ma][1] += t1;
        }

        // ---- O += P V ----
        #pragma unroll
        for (int kt = 0; kt < 4; kt++) {
            uint32_t vf[4][2];
            {
                uint32_t off0 = (uint32_t)((lane * TP_ + kt * 16) * 2);
                uint32_t t0[4], t1[4];
                ldsm4(t0, uV + off0);
                ldsm4(t1, uV + off0 + 16);
                #pragma unroll
                for (int j = 0; j < 4; j++) { vf[j][0] = t0[j]; vf[j][1] = t1[j]; }
            }
            #pragma unroll
            for (int ma = 0; ma < 2; ma++) {
                uint32_t pf[4];
                pf[0] = pack2bf(sc[ma][2 * kt][0],     sc[ma][2 * kt][1]);
                pf[1] = pack2bf(sc[ma][2 * kt][2],     sc[ma][2 * kt][3]);
                pf[2] = pack2bf(sc[ma][2 * kt + 1][0], sc[ma][2 * kt + 1][1]);
                pf[3] = pack2bf(sc[ma][2 * kt + 1][2], sc[ma][2 * kt + 1][3]);
                #pragma unroll
                for (int nd = 0; nd < 4; nd++)
                    mma16816(o[ma][nd], pf, vf[nd]);
            }
        }
        if (kb + 1 < S_ / 64) { CP_WAIT(0); __syncthreads(); }
    }

    // ---- epilogue: reduce l across quad, O /= l, write g_att (b,s,h,d) ----
    const int b = bh >> 3, h = bh & 7;
    const int lrow = lane >> 2, lcol = (lane & 3) * 2;
    #pragma unroll
    for (int ma = 0; ma < 2; ma++)
        #pragma unroll
        for (int hf = 0; hf < 2; hf++) {
            float lt = l[ma][hf];
            lt += __shfl_xor_sync(0xffffffffu, lt, 1);
            lt += __shfl_xor_sync(0xffffffffu, lt, 2);
            float inv = 1.0f / lt;
            int s = q0 + wid * 32 + ma * 16 + lrow + hf * 8;
            #pragma unroll
            for (int nd = 0; nd < 4; nd++) {
                int d = nd * 8 + lcol;
                float2 o2;
                o2.x = o[ma][nd][hf * 2]     * inv;
                o2.y = o[ma][nd][hf * 2 + 1] * inv;
                *(float2*)(g_att + (size_t)(b * S_ + s) * E_ + h * 32 + d) = o2;
            }
        }
}

// ---------------- tensor-core GEMM (K-chunk 32, 2 CTA/SM, 1 sync/iter) --------
template <int KTOT, bool GELU>
__global__ __launch_bounds__(256, 2) void k_gemm(
    const __nv_bfloat16* __restrict__ Ahi, const __nv_bfloat16* __restrict__ Alo,
    const __nv_bfloat16* __restrict__ Bhi, const __nv_bfloat16* __restrict__ Blo,
    const float* __restrict__ bias, const float* __restrict__ res,
    float* __restrict__ outF,
    __nv_bfloat16* __restrict__ outHi, __nv_bfloat16* __restrict__ outLo,
    int Nglob) {
    extern __shared__ __align__(16) char dsm[];
    const int tid = threadIdx.x;
    const int wid = tid >> 5, lane = tid & 31;
    const int n0 = blockIdx.x * 128, m0 = blockIdx.y * 128;
    const int wm = (wid >> 2) * 64;
    const int wn = (wid & 3) * 32;
    const uint32_t uS = s2u(dsm);

    // stage: Ah, Al, Bh, Bl tiles of 128 rows x 32 k-elems (pitch QP_)
    auto loadAsync = [&](int c, int s) {
        const int kc = c * 32;
        const uint32_t base = uS + (uint32_t)(s * GSTG_ * 2);
        const __nv_bfloat16* gp[4] = { Ahi, Alo, Bhi, Blo };
        #pragma unroll
        for (int t = 0; t < 4; t++) {
            const __nv_bfloat16* g = gp[t];
            const int row0 = (t < 2) ? m0 : n0;
            const uint32_t db = base + (uint32_t)(t * GTSZ_ * 2);
            #pragma unroll
            for (int idx = tid; idx < 512; idx += 256) {
                int r = idx >> 2, c4 = idx & 3;
                cp16(db + (uint32_t)((r * QP_ + c4 * 8) * 2),
                     g + (size_t)(row0 + r) * KTOT + kc + c4 * 8);
            }
        }
        CP_COMMIT();
    };

    float acc[4][4][4];
    #pragma unroll
    for (int ma = 0; ma < 4; ma++)
        #pragma unroll
        for (int na = 0; na < 4; na++)
            #pragma unroll
            for (int r = 0; r < 4; r++) acc[ma][na][r] = 0.f;

    const int aRow = (lane & 15);
    const int aK   = (lane >> 4) << 3;
    const int bRow = lane;

    constexpr int NC = KTOT / 32;
    loadAsync(0, 0);
    CP_WAIT(0);
    __syncthreads();

    for (int c = 0; c < NC; c++) {
        const int st = c & 1;
        if (c + 1 < NC) loadAsync(c + 1, st ^ 1);

        const uint32_t base = uS + (uint32_t)(st * GSTG_ * 2);
        const uint32_t uAh = base;
        const uint32_t uAl = base + (uint32_t)(GTSZ_ * 2);
        const uint32_t uBh = base + (uint32_t)(2 * GTSZ_ * 2);
        const uint32_t uBl = base + (uint32_t)(3 * GTSZ_ * 2);

        #pragma unroll
        for (int ks = 0; ks < 2; ks++) {
            const int kk = ks * 16;
            uint32_t bh[4][2], bl[4][2];
            {
                uint32_t off0 = (uint32_t)(((wn + bRow) * QP_ + kk) * 2);
                uint32_t off1 = off0 + 16;
                uint32_t t0[4], t1[4], t2[4], t3[4];
                ldsm4(t0, uBh + off0);  ldsm4(t1, uBh + off1);
                ldsm4(t2, uBl + off0);  ldsm4(t3, uBl + off1);
                #pragma unroll
                for (int na = 0; na < 4; na++) {
                    bh[na][0] = t0[na]; bh[na][1] = t1[na];
                    bl[na][0] = t2[na]; bl[na][1] = t3[na];
                }
            }
            #pragma unroll
            for (int ma = 0; ma < 4; ma++) {
                uint32_t ah[4], al[4];
                uint32_t off = (uint32_t)(((wm + ma * 16 + aRow) * QP_ + kk + aK) * 2);
                ldsm4(ah, uAh + off);
                ldsm4(al, uAl + off);
                #pragma unroll
                for (int na = 0; na < 4; na++) {
                    mma16816(acc[ma][na], ah, bh[na]);
                    mma16816(acc[ma][na], al, bh[na]);
                    mma16816(acc[ma][na], ah, bl[na]);
                }
            }
        }
        if (c + 1 < NC) { CP_WAIT(0); __syncthreads(); }
    }

    const int lrow = lane >> 2, lcol = (lane & 3) * 2;
    float2 bv[4];
    #pragma unroll
    for (int na = 0; na < 4; na++)
        bv[na] = *(const float2*)&bias[n0 + wn + na * 8 + lcol];

    #pragma unroll
    for (int ma = 0; ma < 4; ma++) {
        #pragma unroll
        for (int half = 0; half < 2; half++) {
            int row = m0 + wm + ma * 16 + lrow + half * 8;
            #pragma unroll
            for (int na = 0; na < 4; na++) {
                int col = n0 + wn + na * 8 + lcol;
                float v0 = acc[ma][na][half * 2 + 0] + bv[na].x;
                float v1 = acc[ma][na][half * 2 + 1] + bv[na].y;
                if (GELU) {
                    float g0 = 0.5f * v0 * (1.0f + erff(v0 * 0.7071067811865476f));
                    float g1 = 0.5f * v1 * (1.0f + erff(v1 * 0.7071067811865476f));
                    uint32_t hh, ll;
                    hilo2(g0, g1, hh, ll);
                    *(uint32_t*)(outHi + (size_t)row * Nglob + col) = hh;
                    *(uint32_t*)(outLo + (size_t)row * Nglob + col) = ll;
                } else {
                    float2 r2 = *(const float2*)(res + (size_t)row * Nglob + col);
                    float2 o2;
                    o2.x = v0 + r2.x;
                    o2.y = v1 + r2.y;
                    *(float2*)(outF + (size_t)row * Nglob + col) = o2;
                }
            }
        }
    }
}

// ---------------- launch ----------------
extern "C" void kernel_launch(void* const* d_in, const int* in_sizes, int n_in,
                              void* d_out, int out_size) {
    const float* x   = (const float*)d_in[0];
    const float* pos = (const float*)d_in[1];
    const float* Wq  = (const float*)d_in[2];
    const float* Wk  = (const float*)d_in[3];
    const float* Wv  = (const float*)d_in[4];
    const float* W1  = (const float*)d_in[5];
    const float* b1  = (const float*)d_in[6];
    const float* W2  = (const float*)d_in[7];
    const float* b2  = (const float*)d_in[8];
    float* out = (float*)d_out;

    float *ph, *pxn, *patt, *pres;
    __nv_bfloat16 *prnh, *prnl, *pffh, *pffl, *pw1h, *pw1l, *pw2h, *pw2l;
    cudaGetSymbolAddress((void**)&ph,   g_h);
    cudaGetSymbolAddress((void**)&pxn,  g_xn);
    cudaGetSymbolAddress((void**)&patt, g_att);
    cudaGetSymbolAddress((void**)&pres, g_res);
    cudaGetSymbolAddress((void**)&prnh, g_rnh);
    cudaGetSymbolAddress((void**)&prnl, g_rnl);
    cudaGetSymbolAddress((void**)&pffh, g_ffh);
    cudaGetSymbolAddress((void**)&pffl, g_ffl);
    cudaGetSymbolAddress((void**)&pw1h, g_w1h);
    cudaGetSymbolAddress((void**)&pw1l, g_w1l);
    cudaGetSymbolAddress((void**)&pw2h, g_w2h);
    cudaGetSymbolAddress((void**)&pw2l, g_w2l);

    cudaFuncSetAttribute((const void*)k_gemm<E_, true>,
                         cudaFuncAttributeMaxDynamicSharedMemorySize, SMEM_DYN);
    cudaFuncSetAttribute((const void*)k_gemm<FF_, false>,
                         cudaFuncAttributeMaxDynamicSharedMemorySize, SMEM_DYN);
    cudaFuncSetAttribute((const void*)k_attn2,
                         cudaFuncAttributeMaxDynamicSharedMemorySize, ATT_SMEM);

    k_addpos<<<BS_ * E_ / 256, 256>>>(x, pos);
    k_wconv<<<dim3(FF_ / 32, E_ / 32, L_), 256>>>(W1, pw1h, pw1l, E_, FF_);
    k_wconv<<<dim3(E_ / 32, FF_ / 32, L_), 256>>>(W2, pw2h, pw2l, FF_, E_);

    for (int l = 0; l < L_; l++) {
        const float* wq = Wq + l * H_ * DH_ * DH_;
        const float* wk = Wk + l * H_ * DH_ * DH_;
        const float* wv = Wv + l * H_ * DH_ * DH_;
        const float* bb1 = b1 + l * FF_;
        const float* bb2 = b2 + l * E_;
        const __nv_bfloat16* w1h = pw1h + (size_t)l * FF_ * E_;
        const __nv_bfloat16* w1l = pw1l + (size_t)l * FF_ * E_;
        const __nv_bfloat16* w2h = pw2h + (size_t)l * E_ * FF_;
        const __nv_bfloat16* w2l = pw2l + (size_t)l * E_ * FF_;
        float* hout = (l == L_ - 1) ? out : ph;

        k_ln<<<BS_ / 8, 256>>>(ph, pxn);
        k_qkv<<<dim3(S_ / 64, B_ * H_), 256>>>(pxn, wq, wk, wv);
        k_attn2<<<dim3(S_ / 128, B_ * H_), 128, ATT_SMEM>>>();
        k_add_ln<<<BS_ / 8, 256>>>(patt, ph, pres, prnh, prnl);
        k_gemm<E_, true><<<dim3(FF_ / 128, BS_ / 128), 256, SMEM_DYN>>>(
            prnh, prnl, w1h, w1l, bb1, nullptr, nullptr, pffh, pffl, FF_);
        k_gemm<FF_, false><<<dim3(E_ / 128, BS_ / 128), 256, SMEM_DYN>>>(
            pffh, pffl, w2h, w2l, bb2, pres, hout, nullptr, nullptr, E_);
    }
}

// round 17
// speedup vs baseline: 1.6716x; 1.6716x over previous
#include <cuda_runtime.h>
#include <cuda_fp16.h>
#include <math.h>
#include <stdint.h>

#define B_  32
#define S_  512
#define E_  256
#define H_  8
#define DH_ 32
#define L_  4
#define FF_ 1024
#define BS_ (B_ * S_)          // 16384 rows
#define EPS_ 1e-5f

// ---------------- scratch (allocation-free: __device__ globals) ----------------
__device__ float g_h  [BS_ * E_];
__device__ float g_xn [BS_ * E_];
__device__ float g_att[BS_ * E_];
__device__ float g_res[BS_ * E_];
// fp16 buffers (single-term: fp16 eps 2.4e-4 keeps stream error ~1e-4/layer)
__device__ __align__(256) __half g_qh [BS_ * E_];   // [bh][s][32], pre-scaled
__device__ __align__(256) __half g_kh [BS_ * E_];   // [bh][s][32]
__device__ __align__(256) __half g_vt [BS_ * E_];   // [bh][d][s]  (transposed)
__device__ __align__(256) __half g_rn [BS_ * E_];
__device__ __align__(256) __half g_ff [BS_ * FF_];
__device__ __align__(256) __half g_w1t[L_ * FF_ * E_];   // [l][n=FF][k=E]
__device__ __align__(256) __half g_w2t[L_ * E_ * FF_];   // [l][n=E][k=FF]

// ---------------- mma.sync / cp.async helpers ----------------
__device__ __forceinline__ uint32_t s2u(const void* p) {
    uint32_t a;
    asm("{ .reg .u64 t; cvta.to.shared.u64 t, %1; cvt.u32.u64 %0, t; }" : "=r"(a) : "l"(p));
    return a;
}
__device__ __forceinline__ void ldsm4(uint32_t* r, uint32_t a) {
    asm volatile("ldmatrix.sync.aligned.m8n8.x4.shared.b16 {%0,%1,%2,%3}, [%4];"
                 : "=r"(r[0]), "=r"(r[1]), "=r"(r[2]), "=r"(r[3]) : "r"(a));
}
// fp16 inputs, fp32 accumulate
__device__ __forceinline__ void mma16816(float* c, const uint32_t* a, const uint32_t* b) {
    asm volatile("mma.sync.aligned.m16n8k16.row.col.f32.f16.f16.f32 "
                 "{%0,%1,%2,%3}, {%4,%5,%6,%7}, {%8,%9}, {%0,%1,%2,%3};"
                 : "+f"(c[0]), "+f"(c[1]), "+f"(c[2]), "+f"(c[3])
                 : "r"(a[0]), "r"(a[1]), "r"(a[2]), "r"(a[3]), "r"(b[0]), "r"(b[1]));
}
__device__ __forceinline__ void cp16(uint32_t d, const void* s) {
    asm volatile("cp.async.ca.shared.global [%0], [%1], 16;" :: "r"(d), "l"(s));
}
#define CP_COMMIT() asm volatile("cp.async.commit_group;" ::: "memory")
#define CP_WAIT(n)  asm volatile("cp.async.wait_group %0;" :: "n"(n) : "memory")

__device__ __forceinline__ uint32_t pack2h(float x, float y) {
    __half2 h = __floats2half2_rn(x, y);
    return *(uint32_t*)&h;
}
__device__ __forceinline__ float warp_sum(float v) {
    #pragma unroll
    for (int o = 16; o; o >>= 1) v += __shfl_xor_sync(0xffffffffu, v, o);
    return v;
}

// smem tile pitches (fp16 elems)
#define TP_  72    // 64 k-elems + 8  (V tiles in attention)
#define QP_  40    // 32 k-elems + 8  (Q/K tiles + gemm K-chunk-32 tiles)
#define GTSZ_ (128 * QP_)                      // one gemm tile: 5120 elems
#define GSTG_ (2 * GTSZ_)                      // gemm stage (A, B): 10240 elems
#define SMEM_DYN (2 * GSTG_ * 2)               // 2 stages = 40960 B

// attention dynamic smem layout (elem offsets) -- 2-stage K/V
#define AQ_  0
#define AK_(s) (128 * QP_ + (s) * 64 * QP_)
#define AV_(s) (128 * QP_ + 2 * 64 * QP_ + (s) * 32 * TP_)
#define ATT_SMEM ((128 * QP_ + 2 * 64 * QP_ + 2 * 32 * TP_) * 2)   // 29696 B

// ---------------- elementwise / norm kernels ----------------
__global__ void k_addpos(const float* __restrict__ x, const float* __restrict__ pos) {
    int i = blockIdx.x * blockDim.x + threadIdx.x;
    g_h[i] = x[i] + pos[i & (E_ - 1)];
}

// warp-per-row LayerNorm: 8 rows/block, shfl-only reductions
__global__ __launch_bounds__(256) void k_ln(const float* __restrict__ src,
                                            float* __restrict__ dst) {
    int w = threadIdx.x >> 5, lane = threadIdx.x & 31;
    int row = blockIdx.x * 8 + w;
    const float* p = src + (size_t)row * E_ + lane * 8;
    float4 a = *(const float4*)p;
    float4 b = *(const float4*)(p + 4);
    float s = (a.x + a.y) + (a.z + a.w) + (b.x + b.y) + (b.z + b.w);
    float m = warp_sum(s) * (1.0f / E_);
    a.x -= m; a.y -= m; a.z -= m; a.w -= m;
    b.x -= m; b.y -= m; b.z -= m; b.w -= m;
    float q = a.x * a.x + a.y * a.y + a.z * a.z + a.w * a.w
            + b.x * b.x + b.y * b.y + b.z * b.z + b.w * b.w;
    float r = rsqrtf(warp_sum(q) * (1.0f / E_) + EPS_);
    a.x *= r; a.y *= r; a.z *= r; a.w *= r;
    b.x *= r; b.y *= r; b.z *= r; b.w *= r;
    float* q_ = dst + (size_t)row * E_ + lane * 8;
    *(float4*)q_ = a;
    *(float4*)(q_ + 4) = b;
}

// res = a + b ; rn = LayerNorm(res) -> fp16. warp-per-row.
__global__ __launch_bounds__(256) void k_add_ln(const float* __restrict__ A,
                                                const float* __restrict__ Bp,
                                                float* __restrict__ res,
                                                __half* __restrict__ rn) {
    int w = threadIdx.x >> 5, lane = threadIdx.x & 31;
    int row = blockIdx.x * 8 + w;
    size_t off = (size_t)row * E_ + lane * 8;
    float4 a0 = *(const float4*)(A + off);
    float4 a1 = *(const float4*)(A + off + 4);
    float4 b0 = *(const float4*)(Bp + off);
    float4 b1 = *(const float4*)(Bp + off + 4);
    a0.x += b0.x; a0.y += b0.y; a0.z += b0.z; a0.w += b0.w;
    a1.x += b1.x; a1.y += b1.y; a1.z += b1.z; a1.w += b1.w;
    *(float4*)(res + off) = a0;
    *(float4*)(res + off + 4) = a1;
    float s = (a0.x + a0.y) + (a0.z + a0.w) + (a1.x + a1.y) + (a1.z + a1.w);
    float m = warp_sum(s) * (1.0f / E_);
    float y[8] = { a0.x - m, a0.y - m, a0.z - m, a0.w - m,
                   a1.x - m, a1.y - m, a1.z - m, a1.w - m };
    float q = 0.f;
    #pragma unroll
    for (int j = 0; j < 8; j++) q += y[j] * y[j];
    float r = rsqrtf(warp_sum(q) * (1.0f / E_) + EPS_);
    __align__(16) __half hv[8];
    #pragma unroll
    for (int j = 0; j < 8; j++) hv[j] = __float2half(y[j] * r);
    *(uint4*)(rn + off) = *(uint4*)hv;
}

// weight transpose + fp16: W[l][K][N] fp32 -> T[l][N][K]
__global__ __launch_bounds__(256) void k_wconv(const float* __restrict__ W,
                                               __half* __restrict__ T,
                                               int K, int N) {
    __shared__ float t[32][33];
    int l = blockIdx.z;
    const float* Wl = W + (size_t)l * K * N;
    __half* Tl = T + (size_t)l * K * N;
    int tx = threadIdx.x & 31, ty = threadIdx.x >> 5;
    int k0 = blockIdx.y * 32, n0 = blockIdx.x * 32;
    #pragma unroll
    for (int i = 0; i < 4; i++)
        t[ty + i * 8][tx] = Wl[(size_t)(k0 + ty + i * 8) * N + n0 + tx];
    __syncthreads();
    #pragma unroll
    for (int i = 0; i < 4; i++) {
        int n = n0 + ty + i * 8;
        Tl[(size_t)n * K + k0 + tx] = __float2half(t[tx][ty + i * 8]);
    }
}

// ---------------- QKV projection: fp32 SIMT compute, fp16 outputs -------------
__global__ __launch_bounds__(256) void k_qkv(const float* __restrict__ xn,
                                             const float* __restrict__ Wq,
                                             const float* __restrict__ Wk,
                                             const float* __restrict__ Wv) {
    __shared__ __align__(16) float Xs[64 * 32];
    __shared__ __align__(16) float WsQ[32 * 32];
    __shared__ __align__(16) float WsK[32 * 32];
    __shared__ __align__(16) float WsV[32 * 32];
    __shared__ float vbuf[32][65];
    int tid = threadIdx.x;
    int bh = blockIdx.y;
    int b = bh >> 3, h = bh & 7;
    int s0 = blockIdx.x * 64;

    ((float4*)WsQ)[tid] = ((const float4*)(Wq + h * 1024))[tid];
    ((float4*)WsK)[tid] = ((const float4*)(Wk + h * 1024))[tid];
    ((float4*)WsV)[tid] = ((const float4*)(Wv + h * 1024))[tid];
    #pragma unroll
    for (int it = 0; it < 2; it++) {
        int fi = it * 256 + tid;
        int r = fi >> 3, d4 = fi & 7;
        float4 t = *(const float4*)(xn + (b * S_ + s0 + r) * E_ + h * 32 + d4 * 4);
        *(float4*)(Xs + r * 32 + d4 * 4) = t;
    }
    __syncthreads();

    int w = tid >> 5, lane = tid & 31;
    int r0 = w * 8;
    float aq[8] = {0}, ak[8] = {0}, av[8] = {0};
    #pragma unroll
    for (int d = 0; d < 32; d++) {
        float wq = WsQ[d * 32 + lane];
        float wk = WsK[d * 32 + lane];
        float wv = WsV[d * 32 + lane];
        #pragma unroll
        for (int r = 0; r < 8; r++) {
            float xv = Xs[(r0 + r) * 32 + d];
            aq[r] = fmaf(xv, wq, aq[r]);
            ak[r] = fmaf(xv, wk, ak[r]);
            av[r] = fmaf(xv, wv, av[r]);
        }
    }
    const float qs = 0.17677669529663687f;  // 1/sqrt(32)
    #pragma unroll
    for (int r = 0; r < 8; r++) {
        int idx = (bh * S_ + s0 + r0 + r) * DH_ + lane;
        g_qh[idx] = __float2half(aq[r] * qs);
        g_kh[idx] = __float2half(ak[r]);
        vbuf[lane][r0 + r] = av[r];
    }
    __syncthreads();
    {
        int d = tid >> 3, seg = tid & 7;
        __align__(16) __half hv[8];
        #pragma unroll
        for (int j = 0; j < 8; j++)
            hv[j] = __float2half(vbuf[d][seg * 8 + j]);
        size_t o = (size_t)(bh * DH_ + d) * S_ + s0 + seg * 8;
        *(uint4*)(g_vt + o) = *(uint4*)hv;
    }
}

// ---------------- Flash attention, fp16, no-max softmax ----------------------
// grid (S/128, B*H), 128 threads (4 warps x 32 q-rows). Key block = 64, 2-stage.
__global__ __launch_bounds__(128) void k_attn2() {
    extern __shared__ __align__(16) __half asm_[];
    const int tid = threadIdx.x;
    const int wid = tid >> 5, lane = tid & 31;
    const int bh = blockIdx.y;
    const int q0 = blockIdx.x * 128;
    const uint32_t uS = s2u(asm_);

    // ---- stage Q via cp.async (512 x16B) ----
    #pragma unroll
    for (int it = 0; it < 4; it++) {
        int e = it * 128 + tid;
        int r = e >> 2, c = e & 3;
        cp16(uS + (AQ_ + r * QP_ + c * 8) * 2,
             g_qh + (size_t)(bh * S_ + q0 + r) * DH_ + c * 8);
    }
    CP_COMMIT();

    auto loadKV = [&](int kb, int s) {
        #pragma unroll
        for (int it = 0; it < 2; it++) {
            int e = it * 128 + tid;
            int r = e >> 2, c = e & 3;
            cp16(uS + (AK_(s) + r * QP_ + c * 8) * 2,
                 g_kh + (size_t)(bh * S_ + kb * 64 + r) * DH_ + c * 8);
            int rv = e >> 3, cv = e & 7;
            cp16(uS + (AV_(s) + rv * TP_ + cv * 8) * 2,
                 g_vt + (size_t)(bh * DH_ + rv) * S_ + kb * 64 + cv * 8);
        }
        CP_COMMIT();
    };
    loadKV(0, 0);
    CP_WAIT(0);
    __syncthreads();

    // ---- Q fragments (registers, held across key loop) ----
    const int aRow = lane & 15, aK = (lane >> 4) << 3;
    uint32_t qf[2][2][4];
    #pragma unroll
    for (int ma = 0; ma < 2; ma++)
        #pragma unroll
        for (int kt = 0; kt < 2; kt++)
            ldsm4(qf[ma][kt],
                  uS + (uint32_t)((AQ_ + (wid * 32 + ma * 16 + aRow) * QP_ + kt * 16 + aK) * 2));

    float l[2][2], o[2][4][4];
    #pragma unroll
    for (int ma = 0; ma < 2; ma++)
        #pragma unroll
        for (int hf = 0; hf < 2; hf++) l[ma][hf] = 0.f;
    #pragma unroll
    for (int ma = 0; ma < 2; ma++)
        #pragma unroll
        for (int nd = 0; nd < 4; nd++)
            #pragma unroll
            for (int r = 0; r < 4; r++) o[ma][nd][r] = 0.f;

    for (int kb = 0; kb < S_ / 64; kb++) {
        const int st = kb & 1;
        if (kb + 1 < S_ / 64) loadKV(kb + 1, st ^ 1);

        const uint32_t uK = uS + AK_(st) * 2;
        const uint32_t uV = uS + AV_(st) * 2;

        // ---- S = Q K^T ----
        float sc[2][8][4];
        #pragma unroll
        for (int ma = 0; ma < 2; ma++)
            #pragma unroll
            for (int na = 0; na < 8; na++)
                #pragma unroll
                for (int r = 0; r < 4; r++) sc[ma][na][r] = 0.f;

        #pragma unroll
        for (int ks = 0; ks < 2; ks++) {
            uint32_t kf[8][2];
            #pragma unroll
            for (int rg = 0; rg < 2; rg++) {
                uint32_t off0 = (uint32_t)(((rg * 32 + lane) * QP_ + ks * 16) * 2);
                uint32_t t0[4], t1[4];
                ldsm4(t0, uK + off0);
                ldsm4(t1, uK + off0 + 16);
                #pragma unroll
                for (int j = 0; j < 4; j++) {
                    kf[rg * 4 + j][0] = t0[j]; kf[rg * 4 + j][1] = t1[j];
                }
            }
            #pragma unroll
            for (int ma = 0; ma < 2; ma++)
                #pragma unroll
                for (int na = 0; na < 8; na++)
                    mma16816(sc[ma][na], qf[ma][ks], kf[na]);
        }

        // ---- p = exp(min(s,30)); accumulate per-thread partial denominator ----
        #pragma unroll
        for (int ma = 0; ma < 2; ma++) {
            float t0 = 0.f, t1 = 0.f;
            #pragma unroll
            for (int na = 0; na < 8; na++) {
                float p0 = __expf(fminf(sc[ma][na][0], 30.f));
                float p1 = __expf(fminf(sc[ma][na][1], 30.f));
                float p2 = __expf(fminf(sc[ma][na][2], 30.f));
                float p3 = __expf(fminf(sc[ma][na][3], 30.f));
                sc[ma][na][0] = p0; sc[ma][na][1] = p1;
                sc[ma][na][2] = p2; sc[ma][na][3] = p3;
                t0 += p0 + p1;
                t1 += p2 + p3;
            }
            l[ma][0] += t0;
            l[ma][1] += t1;
        }

        // ---- O += P V ----
        #pragma unroll
        for (int kt = 0; kt < 4; kt++) {
            uint32_t vf[4][2];
            {
                uint32_t off0 = (uint32_t)((lane * TP_ + kt * 16) * 2);
                uint32_t t0[4], t1[4];
                ldsm4(t0, uV + off0);
                ldsm4(t1, uV + off0 + 16);
                #pragma unroll
                for (int j = 0; j < 4; j++) { vf[j][0] = t0[j]; vf[j][1] = t1[j]; }
            }
            #pragma unroll
            for (int ma = 0; ma < 2; ma++) {
                uint32_t pf[4];
                pf[0] = pack2h(sc[ma][2 * kt][0],     sc[ma][2 * kt][1]);
                pf[1] = pack2h(sc[ma][2 * kt][2],     sc[ma][2 * kt][3]);
                pf[2] = pack2h(sc[ma][2 * kt + 1][0], sc[ma][2 * kt + 1][1]);
                pf[3] = pack2h(sc[ma][2 * kt + 1][2], sc[ma][2 * kt + 1][3]);
                #pragma unroll
                for (int nd = 0; nd < 4; nd++)
                    mma16816(o[ma][nd], pf, vf[nd]);
            }
        }
        if (kb + 1 < S_ / 64) { CP_WAIT(0); __syncthreads(); }
    }

    // ---- epilogue: reduce l across quad, O /= l, write g_att (b,s,h,d) ----
    const int b = bh >> 3, h = bh & 7;
    const int lrow = lane >> 2, lcol = (lane & 3) * 2;
    #pragma unroll
    for (int ma = 0; ma < 2; ma++)
        #pragma unroll
        for (int hf = 0; hf < 2; hf++) {
            float lt = l[ma][hf];
            lt += __shfl_xor_sync(0xffffffffu, lt, 1);
            lt += __shfl_xor_sync(0xffffffffu, lt, 2);
            float inv = 1.0f / lt;
            int s = q0 + wid * 32 + ma * 16 + lrow + hf * 8;
            #pragma unroll
            for (int nd = 0; nd < 4; nd++) {
                int d = nd * 8 + lcol;
                float2 o2;
                o2.x = o[ma][nd][hf * 2]     * inv;
                o2.y = o[ma][nd][hf * 2 + 1] * inv;
                *(float2*)(g_att + (size_t)(b * S_ + s) * E_ + h * 32 + d) = o2;
            }
        }
}

// ---------------- tensor-core GEMM (fp16 single-term, K-chunk 32) -------------
template <int KTOT, bool GELU>
__global__ __launch_bounds__(256, 2) void k_gemm(
    const __half* __restrict__ A, const __half* __restrict__ Bw,
    const float* __restrict__ bias, const float* __restrict__ res,
    float* __restrict__ outF, __half* __restrict__ out16,
    int Nglob) {
    extern __shared__ __align__(16) char dsm[];
    const int tid = threadIdx.x;
    const int wid = tid >> 5, lane = tid & 31;
    const int n0 = blockIdx.x * 128, m0 = blockIdx.y * 128;
    const int wm = (wid >> 2) * 64;
    const int wn = (wid & 3) * 32;
    const uint32_t uS = s2u(dsm);

    // stage: A, B tiles of 128 rows x 32 k-elems (pitch QP_)
    auto loadAsync = [&](int c, int s) {
        const int kc = c * 32;
        const uint32_t base = uS + (uint32_t)(s * GSTG_ * 2);
        const __half* gp[2] = { A, Bw };
        #pragma unroll
        for (int t = 0; t < 2; t++) {
            const __half* g = gp[t];
            const int row0 = (t == 0) ? m0 : n0;
            const uint32_t db = base + (uint32_t)(t * GTSZ_ * 2);
            #pragma unroll
            for (int idx = tid; idx < 512; idx += 256) {
                int r = idx >> 2, c4 = idx & 3;
                cp16(db + (uint32_t)((r * QP_ + c4 * 8) * 2),
                     g + (size_t)(row0 + r) * KTOT + kc + c4 * 8);
            }
        }
        CP_COMMIT();
    };

    float acc[4][4][4];
    #pragma unroll
    for (int ma = 0; ma < 4; ma++)
        #pragma unroll
        for (int na = 0; na < 4; na++)
            #pragma unroll
            for (int r = 0; r < 4; r++) acc[ma][na][r] = 0.f;

    const int aRow = (lane & 15);
    const int aK   = (lane >> 4) << 3;
    const int bRow = lane;

    constexpr int NC = KTOT / 32;
    loadAsync(0, 0);
    CP_WAIT(0);
    __syncthreads();

    for (int c = 0; c < NC; c++) {
        const int st = c & 1;
        if (c + 1 < NC) loadAsync(c + 1, st ^ 1);

        const uint32_t base = uS + (uint32_t)(st * GSTG_ * 2);
        const uint32_t uA = base;
        const uint32_t uB = base + (uint32_t)(GTSZ_ * 2);

        #pragma unroll
        for (int ks = 0; ks < 2; ks++) {
            const int kk = ks * 16;
            uint32_t bf[4][2];
            {
                uint32_t off0 = (uint32_t)(((wn + bRow) * QP_ + kk) * 2);
                uint32_t t0[4], t1[4];
                ldsm4(t0, uB + off0);
                ldsm4(t1, uB + off0 + 16);
                #pragma unroll
                for (int na = 0; na < 4; na++) { bf[na][0] = t0[na]; bf[na][1] = t1[na]; }
            }
            #pragma unroll
            for (int ma = 0; ma < 4; ma++) {
                uint32_t af[4];
                ldsm4(af, uA + (uint32_t)(((wm + ma * 16 + aRow) * QP_ + kk + aK) * 2));
                #pragma unroll
                for (int na = 0; na < 4; na++)
                    mma16816(acc[ma][na], af, bf[na]);
            }
        }
        if (c + 1 < NC) { CP_WAIT(0); __syncthreads(); }
    }

    const int lrow = lane >> 2, lcol = (lane & 3) * 2;
    float2 bv[4];
    #pragma unroll
    for (int na = 0; na < 4; na++)
        bv[na] = *(const float2*)&bias[n0 + wn + na * 8 + lcol];

    #pragma unroll
    for (int ma = 0; ma < 4; ma++) {
        #pragma unroll
        for (int half = 0; half < 2; half++) {
            int row = m0 + wm + ma * 16 + lrow + half * 8;
            #pragma unroll
            for (int na = 0; na < 4; na++) {
                int col = n0 + wn + na * 8 + lcol;
                float v0 = acc[ma][na][half * 2 + 0] + bv[na].x;
                float v1 = acc[ma][na][half * 2 + 1] + bv[na].y;
                if (GELU) {
                    float g0 = 0.5f * v0 * (1.0f + erff(v0 * 0.7071067811865476f));
                    float g1 = 0.5f * v1 * (1.0f + erff(v1 * 0.7071067811865476f));
                    *(uint32_t*)(out16 + (size_t)row * Nglob + col) = pack2h(g0, g1);
                } else {
                    float2 r2 = *(const float2*)(res + (size_t)row * Nglob + col);
                    float2 o2;
                    o2.x = v0 + r2.x;
                    o2.y = v1 + r2.y;
                    *(float2*)(outF + (size_t)row * Nglob + col) = o2;
                }
            }
        }
    }
}

// ---------------- launch ----------------
extern "C" void kernel_launch(void* const* d_in, const int* in_sizes, int n_in,
                              void* d_out, int out_size) {
    const float* x   = (const float*)d_in[0];
    const float* pos = (const float*)d_in[1];
    const float* Wq  = (const float*)d_in[2];
    const float* Wk  = (const float*)d_in[3];
    const float* Wv  = (const float*)d_in[4];
    const float* W1  = (const float*)d_in[5];
    const float* b1  = (const float*)d_in[6];
    const float* W2  = (const float*)d_in[7];
    const float* b2  = (const float*)d_in[8];
    float* out = (float*)d_out;

    float *ph, *pxn, *patt, *pres;
    __half *prn, *pff, *pw1t, *pw2t;
    cudaGetSymbolAddress((void**)&ph,   g_h);
    cudaGetSymbolAddress((void**)&pxn,  g_xn);
    cudaGetSymbolAddress((void**)&patt, g_att);
    cudaGetSymbolAddress((void**)&pres, g_res);
    cudaGetSymbolAddress((void**)&prn,  g_rn);
    cudaGetSymbolAddress((void**)&pff,  g_ff);
    cudaGetSymbolAddress((void**)&pw1t, g_w1t);
    cudaGetSymbolAddress((void**)&pw2t, g_w2t);

    cudaFuncSetAttribute((const void*)k_gemm<E_, true>,
                         cudaFuncAttributeMaxDynamicSharedMemorySize, SMEM_DYN);
    cudaFuncSetAttribute((const void*)k_gemm<FF_, false>,
                         cudaFuncAttributeMaxDynamicSharedMemorySize, SMEM_DYN);
    cudaFuncSetAttribute((const void*)k_attn2,
                         cudaFuncAttributeMaxDynamicSharedMemorySize, ATT_SMEM);

    k_addpos<<<BS_ * E_ / 256, 256>>>(x, pos);
    k_wconv<<<dim3(FF_ / 32, E_ / 32, L_), 256>>>(W1, pw1t, E_, FF_);
    k_wconv<<<dim3(E_ / 32, FF_ / 32, L_), 256>>>(W2, pw2t, FF_, E_);

    for (int l = 0; l < L_; l++) {
        const float* wq = Wq + l * H_ * DH_ * DH_;
        const float* wk = Wk + l * H_ * DH_ * DH_;
        const float* wv = Wv + l * H_ * DH_ * DH_;
        const float* bb1 = b1 + l * FF_;
        const float* bb2 = b2 + l * E_;
        const __half* w1t = pw1t + (size_t)l * FF_ * E_;
        const __half* w2t = pw2t + (size_t)l * E_ * FF_;
        float* hout = (l == L_ - 1) ? out : ph;

        k_ln<<<BS_ / 8, 256>>>(ph, pxn);
        k_qkv<<<dim3(S_ / 64, B_ * H_), 256>>>(pxn, wq, wk, wv);
        k_attn2<<<dim3(S_ / 128, B_ * H_), 128, ATT_SMEM>>>();
        k_add_ln<<<BS_ / 8, 256>>>(patt, ph, pres, prn);
        k_gemm<E_, true><<<dim3(FF_ / 128, BS_ / 128), 256, SMEM_DYN>>>(
            prn, w1t, bb1, nullptr, nullptr, pff, FF_);
        k_gemm<FF_, false><<<dim3(E_ / 128, BS_ / 128), 256, SMEM_DYN>>>(
            pff, w2t, bb2, pres, hout, nullptr, E_);
    }
}